// round 1
// baseline (speedup 1.0000x reference)
#include <cuda_runtime.h>
#include <cstdint>

// PatchTransformer: paste 8 translated, bilinearly-resampled 256x256x3 patches
// onto a 3x1024x1024 image. Exact-fp replication of the reference's
// grid_sample arithmetic (rn intrinsics block FMA contraction) because the
// reference gates on mask == 1.0 and adv == 0.0 equality.

#define S 1024
#define PS 256
#define NPATCH 8

__global__ __launch_bounds__(256)
void patch_transformer_kernel(const float* __restrict__ patches,   // [8,3,256,256]
                              const float* __restrict__ locs,      // [8,2]
                              const float* __restrict__ clean,     // [3,1024,1024]
                              float* __restrict__ out)             // [3,1024,1024]
{
    __shared__ float sloc[2 * NPATCH];
    int tid = threadIdx.y * blockDim.x + threadIdx.x;
    if (tid < 2 * NPATCH) sloc[tid] = locs[tid];
    __syncthreads();

    int w = blockIdx.x * blockDim.x + threadIdx.x;
    int h = blockIdx.y * blockDim.y + threadIdx.y;
    if (w >= S || h >= S) return;

    const int pix = h * S + w;
    float out0 = clean[pix];
    float out1 = clean[pix + S * S];
    float out2 = clean[pix + 2 * S * S];

    // Normalized grid coords (exact in fp32: powers of two).
    // xs = (w+0.5)*2/1024 - 1 ; ys likewise with h.
    const float gx = __fadd_rn(__fmul_rn(__fmul_rn(__fadd_rn((float)w, 0.5f), 2.0f),
                                         (1.0f / 1024.0f)), -1.0f);
    const float gy = __fadd_rn(__fmul_rn(__fmul_rn(__fadd_rn((float)h, 0.5f), 2.0f),
                                         (1.0f / 1024.0f)), -1.0f);

    #pragma unroll 1
    for (int n = 0; n < NPATCH; ++n) {
        const float lx = sloc[2 * n + 0];
        const float ly = sloc[2 * n + 1];

        // grid = gx - lx (one rounded sub, matching einsum 1*gx + 0*gy + (-lx)*1)
        const float grx = __fadd_rn(gx, -lx);
        const float gry = __fadd_rn(gy, -ly);

        // x = ((grid_x + 1) * 1024 - 1) * 0.5, each step rn-rounded like the reference
        const float x = __fmul_rn(__fadd_rn(__fmul_rn(__fadd_rn(grx, 1.0f), 1024.0f), -1.0f), 0.5f);
        const float y = __fmul_rn(__fadd_rn(__fmul_rn(__fadd_rn(gry, 1.0f), 1024.0f), -1.0f), 0.5f);

        const float x0f = floorf(x);
        const float y0f = floorf(y);
        const int ix0 = (int)x0f;
        const int iy0 = (int)y0f;

        // Footprint reject: patch data nonzero only when some tap hits [0,256)^2.
        // Outside this, adv == 0 identically -> composite keeps previous value.
        if ((unsigned)(ix0 + 1) > 256u || (unsigned)(iy0 + 1) > 256u) continue;

        const float wx1 = __fadd_rn(x, -x0f);
        const float wx0 = __fadd_rn(1.0f, -wx1);
        const float wy1 = __fadd_rn(y, -y0f);
        const float wy0 = __fadd_rn(1.0f, -wy1);

        const float w00 = __fmul_rn(wy0, wx0);
        const float w01 = __fmul_rn(wy0, wx1);
        const float w10 = __fmul_rn(wy1, wx0);
        const float w11 = __fmul_rn(wy1, wx1);

        // Frame-validity (1024^2) flags. In-footprint, ix0<=255 and ix0+1<=256,
        // so only the >=0 side can fail.
        const bool vx0 = (ix0 >= 0);
        const bool vy0 = (iy0 >= 0);
        // vx1 / vy1 are always true inside the footprint (ix0+1 >= 0, <= 256 < 1024).

        // mask_w = sum of valid*weight, left-associated like the reference.
        const float m = __fadd_rn(__fadd_rn(__fadd_rn(
                            (vy0 && vx0) ? w00 : 0.0f,
                            vy0 ? w01 : 0.0f),
                            vx0 ? w10 : 0.0f),
                            w11);
        if (m != 1.0f) continue;

        // Patch taps: nonzero only inside [0,256)^2 of the padded image.
        const bool cx0 = (ix0 >= 0);
        const bool cx1 = (ix0 <= PS - 2);   // ix0+1 <= 255
        const bool cy0 = (iy0 >= 0);
        const bool cy1 = (iy0 <= PS - 2);

        const bool t00v = cy0 && cx0;
        const bool t01v = cy0 && cx1;
        const bool t10v = cy1 && cx0;
        const bool t11v = cy1 && cx1;
        if (!(t00v | t01v | t10v | t11v)) continue;

        const float* P = patches + (size_t)n * 3 * PS * PS;
        const int o00 = iy0 * PS + ix0;

        #pragma unroll
        for (int c = 0; c < 3; ++c) {
            const float* B = P + c * PS * PS;
            const float t00 = t00v ? __fmul_rn(__ldg(B + o00),            w00) : 0.0f;
            const float t01 = t01v ? __fmul_rn(__ldg(B + o00 + 1),        w01) : 0.0f;
            const float t10 = t10v ? __fmul_rn(__ldg(B + o00 + PS),       w10) : 0.0f;
            const float t11 = t11v ? __fmul_rn(__ldg(B + o00 + PS + 1),   w11) : 0.0f;
            const float p = __fadd_rn(__fadd_rn(__fadd_rn(t00, t01), t10), t11);
            if (p != 0.0f) {
                if (c == 0) out0 = p;
                else if (c == 1) out1 = p;
                else out2 = p;
            }
        }
    }

    out[pix]             = out0;
    out[pix + S * S]     = out1;
    out[pix + 2 * S * S] = out2;
}

extern "C" void kernel_launch(void* const* d_in, const int* in_sizes, int n_in,
                              void* d_out, int out_size) {
    const float* patches = (const float*)d_in[0];   // (8,3,256,256)
    const float* locs    = (const float*)d_in[1];   // (8,2)
    const float* clean   = (const float*)d_in[2];   // (3,1024,1024)
    float* out = (float*)d_out;                     // (1,3,1024,1024)

    dim3 block(32, 8);
    dim3 grid(S / 32, S / 8);
    patch_transformer_kernel<<<grid, block>>>(patches, locs, clean, out);
}